// round 15
// baseline (speedup 1.0000x reference)
#include <cuda_runtime.h>
#include <cuda_bf16.h>
#include <cuda_fp16.h>
#include <math.h>
#include <stdint.h>

#define NN 50000
#define EE 800000
#define DD 128
#define HH 8
#define CNT_PAD 53248   // 1024 threads * 52 ints

// ---------------- scratch (static device arrays, no allocation) -------------
__device__ unsigned int g_Qh[NN * 64];
__device__ unsigned int g_Kh[NN * 64];
__device__ unsigned int g_Vh[NN * 64];
__device__ float g_h[NN * DD];
__device__ unsigned int g_xhi[NN * 64];
__device__ unsigned int g_xlo[NN * 64];
__device__ unsigned int g_thi[NN * 64];
__device__ unsigned int g_tlo[NN * 64];
__device__ uint2 g_wfh[4][4096];
__device__ uint2 g_wfl[4][4096];
// CSR by destination
__device__ __align__(16) int g_cnt[CNT_PAD];
__device__ int g_rowptr[NN + 1];
__device__ int g_off[NN];
__device__ int g_esrc[EE];

// ---------------- helpers ---------------------------------------------------
__device__ __forceinline__ unsigned int smem_u32(const void* p) {
    unsigned int a;
    asm("{ .reg .u64 t; cvta.to.shared.u64 t, %1; cvt.u32.u64 %0, t; }" : "=r"(a) : "l"(p));
    return a;
}

__device__ __forceinline__ unsigned int pack_bf(float a, float b) {
    __nv_bfloat162 t = __floats2bfloat162_rn(a, b);
    return *reinterpret_cast<unsigned int*>(&t);
}

__device__ __forceinline__ unsigned int pack_h2(float a, float b) {
    __half2 t = __floats2half2_rn(a, b);
    return *reinterpret_cast<unsigned int*>(&t);
}

__device__ __forceinline__ float2 unpack_h2(unsigned int u) {
    return __half22float2(*reinterpret_cast<__half2*>(&u));
}

#define MMA_BF16(c, a, b0v, b1v)                                               \
    asm volatile("mma.sync.aligned.m16n8k16.row.col.f32.bf16.bf16.f32 "        \
                 "{%0,%1,%2,%3}, {%4,%5,%6,%7}, {%8,%9}, {%0,%1,%2,%3};"       \
                 : "+f"((c)[0]), "+f"((c)[1]), "+f"((c)[2]), "+f"((c)[3])      \
                 : "r"((a)[0]), "r"((a)[1]), "r"((a)[2]), "r"((a)[3]),         \
                   "r"(b0v), "r"(b1v))

#define LDMATRIX_X4(r, addr)                                                   \
    asm volatile("ldmatrix.sync.aligned.m8n8.x4.shared.b16 {%0,%1,%2,%3}, [%4];" \
                 : "=r"((r)[0]), "=r"((r)[1]), "=r"((r)[2]), "=r"((r)[3])      \
                 : "r"(addr))

// ---------------------------------------------------------------------------
// Convert x -> bf16 hi/lo pairs; also zero the CSR histogram counters.
// ---------------------------------------------------------------------------
__global__ void convert_x(const float* __restrict__ x) {
    int i = blockIdx.x * 256 + threadIdx.x;
    if (i < CNT_PAD) g_cnt[i] = 0;
    if (i >= NN * 64) return;
    float2 v = reinterpret_cast<const float2*>(x)[i];
    __nv_bfloat162 hp = __floats2bfloat162_rn(v.x, v.y);
    float l0 = v.x - __bfloat162float(hp.x);
    float l1 = v.y - __bfloat162float(hp.y);
    g_xhi[i] = *reinterpret_cast<unsigned int*>(&hp);
    g_xlo[i] = pack_bf(l0, l1);
}

// ---------------------------------------------------------------------------
// CSR build: histogram (x4) -> single-block scan (int4) -> scatter (x4)
// ---------------------------------------------------------------------------
__global__ void hist_kernel(const int* __restrict__ dst) {
    int i = blockIdx.x * 256 + threadIdx.x;
    if (i < EE / 4) {
        int4 d = reinterpret_cast<const int4*>(dst)[i];
        atomicAdd(&g_cnt[d.x], 1);
        atomicAdd(&g_cnt[d.y], 1);
        atomicAdd(&g_cnt[d.z], 1);
        atomicAdd(&g_cnt[d.w], 1);
    }
}

__global__ void scan_kernel() {
    __shared__ int ssum[1024];
    const int CH4 = 13;
    int t = threadIdx.x;
    int base4 = t * CH4;

    int4 vals[CH4];
    int local = 0;
#pragma unroll
    for (int i = 0; i < CH4; i++) {
        vals[i] = reinterpret_cast<const int4*>(g_cnt)[base4 + i];
        local += vals[i].x + vals[i].y + vals[i].z + vals[i].w;
    }
    ssum[t] = local;
    __syncthreads();
    for (int o = 1; o < 1024; o <<= 1) {
        int u = (t >= o) ? ssum[t - o] : 0;
        __syncthreads();
        ssum[t] += u;
        __syncthreads();
    }
    int run = ssum[t] - local;
    int base = t * 52;
#pragma unroll
    for (int i = 0; i < CH4; i++) {
        int idx = base + i * 4;
        int4 v = vals[i];
        if (idx     < NN) { g_rowptr[idx]     = run; g_off[idx]     = run; } run += v.x;
        if (idx + 1 < NN) { g_rowptr[idx + 1] = run; g_off[idx + 1] = run; } run += v.y;
        if (idx + 2 < NN) { g_rowptr[idx + 2] = run; g_off[idx + 2] = run; } run += v.z;
        if (idx + 3 < NN) { g_rowptr[idx + 3] = run; g_off[idx + 3] = run; } run += v.w;
    }
    if (t == 1023) g_rowptr[NN] = run;
}

__global__ void scatter_kernel(const int* __restrict__ src, const int* __restrict__ dst) {
    int i = blockIdx.x * 256 + threadIdx.x;
    if (i < EE / 4) {
        int4 d = reinterpret_cast<const int4*>(dst)[i];
        int4 s = reinterpret_cast<const int4*>(src)[i];
        int p0 = atomicAdd(&g_off[d.x], 1); g_esrc[p0] = s.x;
        int p1 = atomicAdd(&g_off[d.y], 1); g_esrc[p1] = s.y;
        int p2 = atomicAdd(&g_off[d.z], 1); g_esrc[p2] = s.z;
        int p3 = atomicAdd(&g_off[d.w], 1); g_esrc[p3] = s.w;
    }
}

// ---------------------------------------------------------------------------
// Bake W (4 matrices) into mma.sync B-fragment layout (hi + lo splits).
// ---------------------------------------------------------------------------
__global__ void convert_w(const float* __restrict__ Wq, const float* __restrict__ Wk,
                          const float* __restrict__ Wv, const float* __restrict__ Wo) {
    int m = blockIdx.y;
    const float* W = (m == 0) ? Wq : (m == 1) ? Wk : (m == 2) ? Wv : Wo;
    int i = blockIdx.x * 256 + threadIdx.x;
    if (i >= 4096) return;
    int lane = i & 31, nn = (i >> 5) & 15, kk = i >> 9;
    int g = lane >> 2, tig = lane & 3;
    int k0 = kk * 16 + 2 * tig;
    int col = nn * 8 + g;

    float w00 = W[(k0)     * 128 + col];
    float w01 = W[(k0 + 1) * 128 + col];
    float w10 = W[(k0 + 8) * 128 + col];
    float w11 = W[(k0 + 9) * 128 + col];

    __nv_bfloat16 h00 = __float2bfloat16_rn(w00);
    __nv_bfloat16 h01 = __float2bfloat16_rn(w01);
    __nv_bfloat16 h10 = __float2bfloat16_rn(w10);
    __nv_bfloat16 h11 = __float2bfloat16_rn(w11);

    g_wfh[m][i] = make_uint2(pack_bf(w00, w01), pack_bf(w10, w11));
    g_wfl[m][i] = make_uint2(
        pack_bf(w00 - __bfloat162float(h00), w01 - __bfloat162float(h01)),
        pack_bf(w10 - __bfloat162float(h10), w11 - __bfloat162float(h11)));
}

// ---------------------------------------------------------------------------
// mma.sync GEMM (R13-proven): warp tile 16x128 as two 16x64 halves,
// term-major distance-4 chains, rolling B prefetch.
// qkv mode (is_out=0): epilogue packs D+bias to fp16 half2 -> g_Qh/g_Kh/g_Vh
// out mode (is_out=1): out = g_h + relu(D + bo) fp32
// ---------------------------------------------------------------------------
__global__ void __launch_bounds__(256, 3)
mma_gemm(int a_is_t, int w_base, const float* __restrict__ b0,
         const float* __restrict__ b1, const float* __restrict__ b2,
         float* __restrict__ dout, int is_out) {
    extern __shared__ char smem[];
    const int A_STRIDE_B = 272;
    const int OFF_LO = 128 * A_STRIDE_B;
    int t = threadIdx.x, warp = t >> 5, lane = t & 31;
    int sel = blockIdx.y;
    int row0 = blockIdx.x * 128;

    const unsigned int* __restrict__ Ahi = a_is_t ? g_thi : g_xhi;
    const unsigned int* __restrict__ Alo = a_is_t ? g_tlo : g_xlo;
    const uint2* __restrict__ wfh = g_wfh[w_base + sel];
    const uint2* __restrict__ wfl = g_wfl[w_base + sel];
    const float* bias = is_out ? b0 : (sel == 0 ? b0 : sel == 1 ? b1 : b2);
    unsigned int* oph = (sel == 0) ? g_Qh : (sel == 1) ? g_Kh : g_Vh;

    for (int i = t; i < 8192; i += 256) {
        int row = i >> 6, p = i & 63;
        int grow = row0 + row;
        unsigned int vh = 0, vl = 0;
        if (grow < NN) { vh = Ahi[grow * 64 + p]; vl = Alo[grow * 64 + p]; }
        int off = row * A_STRIDE_B + p * 4;
        *reinterpret_cast<unsigned int*>(smem + off)          = vh;
        *reinterpret_cast<unsigned int*>(smem + OFF_LO + off) = vl;
    }
    __syncthreads();

    int rowsel = (lane & 7) | (((lane >> 3) & 1) << 3);
    int colblk = lane >> 4;
    unsigned int sb = smem_u32(smem);
    unsigned int a_addr = sb + (warp * 16 + rowsel) * A_STRIDE_B + colblk * 16;

    int g = lane >> 2, tig = lane & 3;
    int r_lo = row0 + warp * 16 + g;
    int r_hi = r_lo + 8;

#pragma unroll 1
    for (int half = 0; half < 2; half++) {
        const uint2* bh_base = wfh + half * 8 * 32 + lane;
        const uint2* bl_base = wfl + half * 8 * 32 + lane;

        float acc[8][4];
#pragma unroll
        for (int nn = 0; nn < 8; nn++)
#pragma unroll
            for (int c = 0; c < 4; c++) acc[nn][c] = 0.f;

        uint2 bhA[4], blA[4];
#pragma unroll
        for (int i = 0; i < 4; i++) {
            bhA[i] = __ldg(bh_base + i * 32);
            blA[i] = __ldg(bl_base + i * 32);
        }

#pragma unroll 1
        for (int kk = 0; kk < 8; kk++) {
            unsigned int a_hi[4], a_lo[4];
            LDMATRIX_X4(a_hi, a_addr + kk * 32);
            LDMATRIX_X4(a_lo, a_addr + OFF_LO + kk * 32);

            uint2 bhB[4], blB[4];
#pragma unroll
            for (int i = 0; i < 4; i++) {
                bhB[i] = __ldg(bh_base + (kk * 16 + 4 + i) * 32);
                blB[i] = __ldg(bl_base + (kk * 16 + 4 + i) * 32);
            }

#pragma unroll
            for (int i = 0; i < 4; i++) MMA_BF16(acc[i], a_hi, bhA[i].x, bhA[i].y);
#pragma unroll
            for (int i = 0; i < 4; i++) MMA_BF16(acc[i], a_hi, blA[i].x, blA[i].y);
#pragma unroll
            for (int i = 0; i < 4; i++) MMA_BF16(acc[i], a_lo, bhA[i].x, bhA[i].y);

            if (kk < 7) {
#pragma unroll
                for (int i = 0; i < 4; i++) {
                    bhA[i] = __ldg(bh_base + ((kk + 1) * 16 + i) * 32);
                    blA[i] = __ldg(bl_base + ((kk + 1) * 16 + i) * 32);
                }
            }

#pragma unroll
            for (int i = 0; i < 4; i++) MMA_BF16(acc[4 + i], a_hi, bhB[i].x, bhB[i].y);
#pragma unroll
            for (int i = 0; i < 4; i++) MMA_BF16(acc[4 + i], a_hi, blB[i].x, blB[i].y);
#pragma unroll
            for (int i = 0; i < 4; i++) MMA_BF16(acc[4 + i], a_lo, bhB[i].x, bhB[i].y);
        }

#pragma unroll
        for (int nn = 0; nn < 8; nn++) {
            int col = (half * 8 + nn) * 8 + 2 * tig;
            float2 bb = *reinterpret_cast<const float2*>(bias + col);
            if (is_out) {
                if (r_lo < NN) {
                    float2 hv = *reinterpret_cast<const float2*>(g_h + (size_t)r_lo * DD + col);
                    float2 o;
                    o.x = hv.x + fmaxf(acc[nn][0] + bb.x, 0.f);
                    o.y = hv.y + fmaxf(acc[nn][1] + bb.y, 0.f);
                    *reinterpret_cast<float2*>(dout + (size_t)r_lo * DD + col) = o;
                }
                if (r_hi < NN) {
                    float2 hv = *reinterpret_cast<const float2*>(g_h + (size_t)r_hi * DD + col);
                    float2 o;
                    o.x = hv.x + fmaxf(acc[nn][2] + bb.x, 0.f);
                    o.y = hv.y + fmaxf(acc[nn][3] + bb.y, 0.f);
                    *reinterpret_cast<float2*>(dout + (size_t)r_hi * DD + col) = o;
                }
            } else {
                int cidx = (half * 8 + nn) * 4 + tig;   // col/2
                if (r_lo < NN)
                    oph[(size_t)r_lo * 64 + cidx] = pack_h2(acc[nn][0] + bb.x, acc[nn][1] + bb.y);
                if (r_hi < NN)
                    oph[(size_t)r_hi * 64 + cidx] = pack_h2(acc[nn][2] + bb.x, acc[nn][3] + bb.y);
            }
        }
    }
}

// ---------------------------------------------------------------------------
// Fused edge + norm kernel: TWO warps per destination node (CSR, no atomics).
// Each warp accumulates a contiguous half of the node's edge list in
// registers (halves the per-warp serial latency chain); partials combined
// via smem + one __syncthreads. Even warp then does normalize + residual +
// LN1 -> g_h + LN2 -> bf16 split.
// Block = 256 threads = 8 warps = 4 nodes.
// ---------------------------------------------------------------------------
__global__ void __launch_bounds__(256)
edge_norm_kernel(const float* __restrict__ x,
                 const float* __restrict__ gamma1, const float* __restrict__ beta1,
                 const float* __restrict__ gamma2, const float* __restrict__ beta2) {
    __shared__ float s_part[4][5][32];   // [pair][component][lane]
    int wid  = threadIdx.x >> 5;         // 0..7
    int lane = threadIdx.x & 31;
    int gw   = blockIdx.x * 8 + wid;     // global warp
    int node = gw >> 1;
    int sub  = gw & 1;
    int pair = wid >> 1;
    bool active = (node < NN);

    float4 wacc = make_float4(0.f, 0.f, 0.f, 0.f);
    float zacc = 0.f;
    float2 q0 = make_float2(0.f, 0.f), q1 = make_float2(0.f, 0.f);

    if (active) {
        uint2 qq = __ldg(reinterpret_cast<const uint2*>(g_Qh + (size_t)node * 64) + lane);
        q0 = unpack_h2(qq.x); q1 = unpack_h2(qq.y);

        int beg = g_rowptr[node];
        int end = g_rowptr[node + 1];
        int len = end - beg;
        int mid = beg + ((len + 1) >> 1);
        int b = sub ? mid : beg;
        int e = sub ? end : mid;

        int i = b;
        for (; i + 2 <= e; i += 2) {
            int s0 = __ldg(g_esrc + i);
            int s1 = __ldg(g_esrc + i + 1);
            uint2 kq0 = __ldg(reinterpret_cast<const uint2*>(g_Kh + (size_t)s0 * 64) + lane);
            uint2 kq1 = __ldg(reinterpret_cast<const uint2*>(g_Kh + (size_t)s1 * 64) + lane);
            uint2 vq0 = __ldg(reinterpret_cast<const uint2*>(g_Vh + (size_t)s0 * 64) + lane);
            uint2 vq1 = __ldg(reinterpret_cast<const uint2*>(g_Vh + (size_t)s1 * 64) + lane);

            float2 ka = unpack_h2(kq0.x), kb = unpack_h2(kq0.y);
            float2 kc = unpack_h2(kq1.x), kd = unpack_h2(kq1.y);
            float p0 = ka.x * q0.x + ka.y * q0.y + kb.x * q1.x + kb.y * q1.y;
            float p1 = kc.x * q0.x + kc.y * q0.y + kd.x * q1.x + kd.y * q1.y;
            p0 += __shfl_xor_sync(0xffffffffu, p0, 1);
            p1 += __shfl_xor_sync(0xffffffffu, p1, 1);
            p0 += __shfl_xor_sync(0xffffffffu, p0, 2);
            p1 += __shfl_xor_sync(0xffffffffu, p1, 2);

            float sc0 = __expf(fminf(fmaxf(p0 * 0.25f, -5.f), 5.f));
            float sc1 = __expf(fminf(fmaxf(p1 * 0.25f, -5.f), 5.f));

            float2 va = unpack_h2(vq0.x), vb = unpack_h2(vq0.y);
            float2 vc = unpack_h2(vq1.x), vd = unpack_h2(vq1.y);
            wacc.x += va.x * sc0 + vc.x * sc1;
            wacc.y += va.y * sc0 + vc.y * sc1;
            wacc.z += vb.x * sc0 + vd.x * sc1;
            wacc.w += vb.y * sc0 + vd.y * sc1;
            zacc += sc0 + sc1;
        }
        if (i < e) {
            int s = __ldg(g_esrc + i);
            uint2 kq = __ldg(reinterpret_cast<const uint2*>(g_Kh + (size_t)s * 64) + lane);
            uint2 vq = __ldg(reinterpret_cast<const uint2*>(g_Vh + (size_t)s * 64) + lane);
            float2 ka = unpack_h2(kq.x), kb = unpack_h2(kq.y);
            float p = ka.x * q0.x + ka.y * q0.y + kb.x * q1.x + kb.y * q1.y;
            p += __shfl_xor_sync(0xffffffffu, p, 1);
            p += __shfl_xor_sync(0xffffffffu, p, 2);
            float sc = __expf(fminf(fmaxf(p * 0.25f, -5.f), 5.f));
            float2 va = unpack_h2(vq.x), vb = unpack_h2(vq.y);
            wacc.x += va.x * sc; wacc.y += va.y * sc;
            wacc.z += vb.x * sc; wacc.w += vb.y * sc;
            zacc += sc;
        }
    }

    // odd warp publishes its partial
    if (sub == 1) {
        s_part[pair][0][lane] = wacc.x;
        s_part[pair][1][lane] = wacc.y;
        s_part[pair][2][lane] = wacc.z;
        s_part[pair][3][lane] = wacc.w;
        s_part[pair][4][lane] = zacc;
    }
    __syncthreads();
    if (sub == 1 || !active) return;

    wacc.x += s_part[pair][0][lane];
    wacc.y += s_part[pair][1][lane];
    wacc.z += s_part[pair][2][lane];
    wacc.w += s_part[pair][3][lane];
    zacc   += s_part[pair][4][lane];

    float rz = 1.f / (zacc + 1e-3f);
    float4 xv = reinterpret_cast<const float4*>(x + (size_t)node * DD)[lane];

    float4 y;
    y.x = xv.x + wacc.x * rz;
    y.y = xv.y + wacc.y * rz;
    y.z = xv.z + wacc.z * rz;
    y.w = xv.w + wacc.w * rz;

    // --- LN1 ---
    float s  = y.x + y.y + y.z + y.w;
    float sq = y.x * y.x + y.y * y.y + y.z * y.z + y.w * y.w;
#pragma unroll
    for (int o = 16; o > 0; o >>= 1) {
        s  += __shfl_xor_sync(0xffffffffu, s,  o);
        sq += __shfl_xor_sync(0xffffffffu, sq, o);
    }
    float mu  = s * (1.f / DD);
    float var = sq * (1.f / DD) - mu * mu;
    float inv = rsqrtf(var + 1e-5f);

    float4 g1 = reinterpret_cast<const float4*>(gamma1)[lane];
    float4 b1 = reinterpret_cast<const float4*>(beta1)[lane];
    float4 h;
    h.x = (y.x - mu) * inv * g1.x + b1.x;
    h.y = (y.y - mu) * inv * g1.y + b1.y;
    h.z = (y.z - mu) * inv * g1.z + b1.z;
    h.w = (y.w - mu) * inv * g1.w + b1.w;
    reinterpret_cast<float4*>(g_h + (size_t)node * DD)[lane] = h;

    // --- LN2 ---
    float s2  = h.x + h.y + h.z + h.w;
    float sq2 = h.x * h.x + h.y * h.y + h.z * h.z + h.w * h.w;
#pragma unroll
    for (int o = 16; o > 0; o >>= 1) {
        s2  += __shfl_xor_sync(0xffffffffu, s2,  o);
        sq2 += __shfl_xor_sync(0xffffffffu, sq2, o);
    }
    float mu2  = s2 * (1.f / DD);
    float var2 = sq2 * (1.f / DD) - mu2 * mu2;
    float inv2 = rsqrtf(var2 + 1e-5f);

    float4 g2 = reinterpret_cast<const float4*>(gamma2)[lane];
    float4 b2 = reinterpret_cast<const float4*>(beta2)[lane];
    float4 tt;
    tt.x = (h.x - mu2) * inv2 * g2.x + b2.x;
    tt.y = (h.y - mu2) * inv2 * g2.y + b2.y;
    tt.z = (h.z - mu2) * inv2 * g2.z + b2.z;
    tt.w = (h.w - mu2) * inv2 * g2.w + b2.w;

    __nv_bfloat162 h01 = __floats2bfloat162_rn(tt.x, tt.y);
    __nv_bfloat162 h23 = __floats2bfloat162_rn(tt.z, tt.w);
    float l0 = tt.x - __bfloat162float(h01.x);
    float l1 = tt.y - __bfloat162float(h01.y);
    float l2 = tt.z - __bfloat162float(h23.x);
    float l3 = tt.w - __bfloat162float(h23.y);
    int base = node * 64 + lane * 2;
    g_thi[base]     = *reinterpret_cast<unsigned int*>(&h01);
    g_thi[base + 1] = *reinterpret_cast<unsigned int*>(&h23);
    g_tlo[base]     = pack_bf(l0, l1);
    g_tlo[base + 1] = pack_bf(l2, l3);
}

// ---------------------------------------------------------------------------
extern "C" void kernel_launch(void* const* d_in, const int* in_sizes, int n_in,
                              void* d_out, int out_size) {
    const float* x      = (const float*)d_in[0];
    const int*   src    = (const int*)  d_in[1];
    const int*   dst    = (const int*)  d_in[2];
    const float* Wq     = (const float*)d_in[3];
    const float* bq     = (const float*)d_in[4];
    const float* Wk     = (const float*)d_in[5];
    const float* bk     = (const float*)d_in[6];
    const float* Wv     = (const float*)d_in[7];
    const float* bv     = (const float*)d_in[8];
    const float* Wo     = (const float*)d_in[9];
    const float* bo     = (const float*)d_in[10];
    const float* gamma1 = (const float*)d_in[11];
    const float* beta1  = (const float*)d_in[12];
    const float* gamma2 = (const float*)d_in[13];
    const float* beta2  = (const float*)d_in[14];
    float* out = (float*)d_out;

    const int MMA_SMEM = 2 * 128 * 272;  // 69632 B
    cudaFuncSetAttribute(mma_gemm, cudaFuncAttributeMaxDynamicSharedMemorySize, MMA_SMEM);

    // x split (+ zero CSR counters)
    convert_x<<<(NN * 64 + 255) / 256, 256>>>(x);

    // CSR build
    hist_kernel<<<(EE / 4 + 255) / 256, 256>>>(dst);
    scan_kernel<<<1, 1024>>>();
    scatter_kernel<<<(EE / 4 + 255) / 256, 256>>>(src, dst);

    // W fragment bake
    convert_w<<<dim3(16, 4), 256>>>(Wq, Wk, Wv, Wo);

    // QKV projections (mma.sync bf16x3) -> fp16-packed Q/K/V
    dim3 qkv_grid((NN + 127) / 128, 3);
    mma_gemm<<<qkv_grid, 256, MMA_SMEM>>>(0, 0, bq, bk, bv, nullptr, 0);

    // fused edge scores + aggregate + normalize + LN1 + LN2(+split)
    // 2 warps per node: grid = NN nodes * 2 warps / 8 warps per block
    edge_norm_kernel<<<(NN * 2 + 7) / 8, 256>>>(x, gamma1, beta1, gamma2, beta2);

    // output projection + relu + residual
    mma_gemm<<<dim3((NN + 127) / 128, 1), 256, MMA_SMEM>>>(1, 3, bo, bo, bo, out, 1);
}